// round 3
// baseline (speedup 1.0000x reference)
#include <cuda_runtime.h>
#include <cstdint>

// ---------------------------------------------------------------------------
// GraphEncoder: batched dense 2-layer GCN on GB300 (sm_103a)
//   out = nrm @ relu(nrm @ (x W1) + b1) W2 ... with nrm = D^-1/2 (A+I) D^-1/2
// Fused form with ds[i] = rsqrt(1 + rowsum(A)[i]):
//   P'  = ds ∘ (X W)                (row-scaled feature product, tf32-rounded)
//   nrm @ (X W) = ds_i * ( (A @ P')_i + P'_i )
//
// R2: BM=128 BN=256 BK=32, 512 threads (16 warps, warp tile 32x64),
//     double-buffered cp.async, producer-side tf32 rounding of B operands.
// ---------------------------------------------------------------------------

#define DEV_INLINE __device__ __forceinline__

static constexpr int BATCH = 8;
static constexpr int NNODE = 4096;
static constexpr int INC   = 256;
static constexpr int HIDC  = 512;
static constexpr int OUTC  = 256;

// Scratch (allocation-free: __device__ globals)
__device__ float g_ds[BATCH * NNODE];                          // 128 KB
__device__ float g_P1[(size_t)BATCH * NNODE * HIDC];           // 64 MB
__device__ float g_H [(size_t)BATCH * NNODE * HIDC];           // 64 MB
__device__ float g_P2[(size_t)BATCH * NNODE * OUTC];           // 32 MB

// ---------------------------------------------------------------------------
// PTX helpers
// ---------------------------------------------------------------------------
DEV_INLINE uint32_t cvt_tf32(float x) {
    uint32_t r;
    asm("cvt.rna.tf32.f32 %0, %1;" : "=r"(r) : "f"(x));
    return r;
}

DEV_INLINE void mma_m16n8k8_tf32(float* d,
                                 uint32_t a0, uint32_t a1, uint32_t a2, uint32_t a3,
                                 uint32_t b0, uint32_t b1) {
    asm volatile(
        "mma.sync.aligned.m16n8k8.row.col.f32.tf32.tf32.f32 "
        "{%0,%1,%2,%3},{%4,%5,%6,%7},{%8,%9},{%0,%1,%2,%3};"
        : "+f"(d[0]), "+f"(d[1]), "+f"(d[2]), "+f"(d[3])
        : "r"(a0), "r"(a1), "r"(a2), "r"(a3), "r"(b0), "r"(b1));
}

DEV_INLINE void cp_async16(uint32_t saddr, const void* gmem) {
    asm volatile("cp.async.cg.shared.global [%0], [%1], 16;" :: "r"(saddr), "l"(gmem));
}
DEV_INLINE void cp_commit() { asm volatile("cp.async.commit_group;"); }
template <int N> DEV_INLINE void cp_wait() { asm volatile("cp.async.wait_group %0;" :: "n"(N)); }

DEV_INLINE uint32_t smem_u32(const void* p) {
    return (uint32_t)__cvta_generic_to_shared(p);
}

// ---------------------------------------------------------------------------
// ds[row] = rsqrt(1 + sum_j A[row, j]),  one block (256 thr) per row
// ---------------------------------------------------------------------------
__global__ void __launch_bounds__(256) row_ds_kernel(const float* __restrict__ A,
                                                     float* __restrict__ ds) {
    long long row = blockIdx.x;
    const float4* p = (const float4*)(A + row * (long long)NNODE);
    float s = 0.f;
    #pragma unroll 4
    for (int i = threadIdx.x; i < NNODE / 4; i += 256) {
        float4 v = p[i];
        s += (v.x + v.y) + (v.z + v.w);
    }
    #pragma unroll
    for (int o = 16; o; o >>= 1) s += __shfl_xor_sync(0xFFFFFFFFu, s, o);
    __shared__ float ws[8];
    if ((threadIdx.x & 31) == 0) ws[threadIdx.x >> 5] = s;
    __syncthreads();
    if (threadIdx.x == 0) {
        float tot = 0.f;
        #pragma unroll
        for (int i = 0; i < 8; i++) tot += ws[i];
        ds[row] = rsqrtf(tot + 1.0f);
    }
}

// ---------------------------------------------------------------------------
// tf32 tensor-core GEMM, 128x256x32 block tile, 512 threads (16 warps, 4x4),
// warp tile 32x64 = 2x8 m16n8k8 tiles, double-buffered cp.async.
//
//  C = A(MxK, row-major fp32) @ B(KxN, row-major fp32)
//  GCN_EPI : C[i,n] = (relu?)( ds[i] * (acc + B[i,n]) + bias[n] )   (needs M==K)
//  else    : C[i,n] = SCALE_ROWS ? ds[i]*acc : acc   (optionally tf32-rounded)
//  PRE_B   : B already tf32-rounded -> skip cvt on B fragments
// ---------------------------------------------------------------------------
template <bool GCN_EPI, bool RELU, bool SCALE_ROWS, bool PRE_B, bool ROUND_OUT>
__global__ void __launch_bounds__(512, 1) gemm_tf32_kernel(
    const float* __restrict__ Ag, const float* __restrict__ Bg, float* __restrict__ Cg,
    const float* __restrict__ ds, const float* __restrict__ bias,
    int M, int N, int K,
    long long strideAb, long long strideBb, long long strideCb, int dsStride) {

    constexpr int BM = 128, BN = 256, BK = 32;
    constexpr int SA_STRIDE = BK + 4;   // 36: conflict-free A frag loads
    constexpr int SB_STRIDE = BN + 8;   // 264: conflict-free B frag loads
    constexpr int SA_ELEMS = BM * SA_STRIDE;   // 4608
    constexpr int SB_ELEMS = BK * SB_STRIDE;   // 8448

    extern __shared__ float smem[];

    const int b = blockIdx.z;
    const float* Ab = Ag + (long long)b * strideAb;
    const float* Bb = Bg + (long long)b * strideBb;
    float*       Cb = Cg + (long long)b * strideCb;
    const float* dsb = ds + (long long)b * dsStride;

    const int m0 = blockIdx.y * BM;
    const int n0 = blockIdx.x * BN;
    const int tid = threadIdx.x;

    auto loadA = [&](int stage, int kt) {
        float* s = smem + stage * SA_ELEMS;
        #pragma unroll
        for (int i = 0; i < 2; i++) {
            int q = tid + i * 512;          // 0..1023 float4s (128 rows x 8)
            int row = q >> 3;
            int c4  = (q & 7) << 2;
            const float* g = Ab + (long long)(m0 + row) * K + kt + c4;
            cp_async16(smem_u32(s + row * SA_STRIDE + c4), g);
        }
    };
    auto loadB = [&](int stage, int kt) {
        float* s = smem + 2 * SA_ELEMS + stage * SB_ELEMS;
        #pragma unroll
        for (int i = 0; i < 4; i++) {
            int q = tid + i * 512;          // 0..2047 float4s (32 rows x 64)
            int row = q >> 6;
            int c4  = (q & 63) << 2;
            const float* g = Bb + (long long)(kt + row) * N + n0 + c4;
            cp_async16(smem_u32(s + row * SB_STRIDE + c4), g);
        }
    };

    const int warp = tid >> 5, lane = tid & 31;
    const int wm = warp >> 2, wn = warp & 3;       // 4 x 4 warp grid
    const int mW = wm * 32, nW = wn * 64;
    const int gr = lane >> 2, t = lane & 3;

    float acc[2][8][4];
    #pragma unroll
    for (int mi = 0; mi < 2; mi++)
        #pragma unroll
        for (int ni = 0; ni < 8; ni++)
            #pragma unroll
            for (int e = 0; e < 4; e++) acc[mi][ni][e] = 0.f;

    loadA(0, 0); loadB(0, 0); cp_commit();

    const int nK = K / BK;
    int stage = 0;
    for (int kt = 0; kt < nK; kt++) {
        if (kt + 1 < nK) {
            loadA(stage ^ 1, (kt + 1) * BK);
            loadB(stage ^ 1, (kt + 1) * BK);
            cp_commit();
            cp_wait<1>();
        } else {
            cp_wait<0>();
        }
        __syncthreads();

        const float* sA = smem + stage * SA_ELEMS;
        const float* sB = smem + 2 * SA_ELEMS + stage * SB_ELEMS;

        #pragma unroll
        for (int kk = 0; kk < BK; kk += 8) {
            uint32_t afr[2][4], bfr[8][2];
            #pragma unroll
            for (int mi = 0; mi < 2; mi++) {
                int r = mW + mi * 16;
                afr[mi][0] = cvt_tf32(sA[(r + gr)     * SA_STRIDE + kk + t]);
                afr[mi][1] = cvt_tf32(sA[(r + gr + 8) * SA_STRIDE + kk + t]);
                afr[mi][2] = cvt_tf32(sA[(r + gr)     * SA_STRIDE + kk + t + 4]);
                afr[mi][3] = cvt_tf32(sA[(r + gr + 8) * SA_STRIDE + kk + t + 4]);
            }
            #pragma unroll
            for (int ni = 0; ni < 8; ni++) {
                int c = nW + ni * 8 + gr;
                float v0 = sB[(kk + t)     * SB_STRIDE + c];
                float v1 = sB[(kk + t + 4) * SB_STRIDE + c];
                if (PRE_B) {
                    bfr[ni][0] = __float_as_uint(v0);
                    bfr[ni][1] = __float_as_uint(v1);
                } else {
                    bfr[ni][0] = cvt_tf32(v0);
                    bfr[ni][1] = cvt_tf32(v1);
                }
            }
            #pragma unroll
            for (int mi = 0; mi < 2; mi++)
                #pragma unroll
                for (int ni = 0; ni < 8; ni++)
                    mma_m16n8k8_tf32(acc[mi][ni],
                                     afr[mi][0], afr[mi][1], afr[mi][2], afr[mi][3],
                                     bfr[ni][0], bfr[ni][1]);
        }
        __syncthreads();
        stage ^= 1;
    }

    // epilogue
    #pragma unroll
    for (int mi = 0; mi < 2; mi++) {
        #pragma unroll
        for (int ni = 0; ni < 8; ni++) {
            int row0 = m0 + mW + mi * 16 + gr;
            int col  = n0 + nW + ni * 8 + t * 2;
            #pragma unroll
            for (int rr = 0; rr < 2; rr++) {
                int row = row0 + rr * 8;
                float v0 = acc[mi][ni][rr * 2 + 0];
                float v1 = acc[mi][ni][rr * 2 + 1];
                if (GCN_EPI) {
                    float d = dsb[row];
                    float2 sv = *(const float2*)(Bb + (long long)row * N + col);
                    v0 = fmaf(d, v0 + sv.x, bias[col]);
                    v1 = fmaf(d, v1 + sv.y, bias[col + 1]);
                    if (RELU) { v0 = fmaxf(v0, 0.f); v1 = fmaxf(v1, 0.f); }
                } else if (SCALE_ROWS) {
                    float d = dsb[row];
                    v0 *= d; v1 *= d;
                }
                if (ROUND_OUT) {   // producer-side tf32 rounding for PRE_B consumers
                    v0 = __uint_as_float(cvt_tf32(v0));
                    v1 = __uint_as_float(cvt_tf32(v1));
                }
                *(float2*)(Cb + (long long)row * N + col) = make_float2(v0, v1);
            }
        }
    }
}

// ---------------------------------------------------------------------------
// launch
// ---------------------------------------------------------------------------
extern "C" void kernel_launch(void* const* d_in, const int* in_sizes, int n_in,
                              void* d_out, int out_size) {
    const float* x  = (const float*)d_in[0];   // [8,4096,256]
    const float* A  = (const float*)d_in[1];   // [8,4096,4096]
    const float* W1 = (const float*)d_in[2];   // [256,512]
    const float* b1 = (const float*)d_in[3];   // [512]
    const float* W2 = (const float*)d_in[4];   // [512,256]
    const float* b2 = (const float*)d_in[5];   // [256]
    float* out = (float*)d_out;                // [8,4096,256]

    float *ds, *P1, *H, *P2;
    cudaGetSymbolAddress((void**)&ds, g_ds);
    cudaGetSymbolAddress((void**)&P1, g_P1);
    cudaGetSymbolAddress((void**)&H,  g_H);
    cudaGetSymbolAddress((void**)&P2, g_P2);

    constexpr int SMEM_BYTES = (2 * 128 * 36 + 2 * 32 * 264) * 4;  // 104448

    cudaFuncSetAttribute(gemm_tf32_kernel<false, false, true, false, true>,
                         cudaFuncAttributeMaxDynamicSharedMemorySize, SMEM_BYTES);
    cudaFuncSetAttribute(gemm_tf32_kernel<true, true, false, true, false>,
                         cudaFuncAttributeMaxDynamicSharedMemorySize, SMEM_BYTES);
    cudaFuncSetAttribute(gemm_tf32_kernel<true, false, false, true, false>,
                         cudaFuncAttributeMaxDynamicSharedMemorySize, SMEM_BYTES);

    // 1) degree scales
    row_ds_kernel<<<BATCH * NNODE, 256>>>(A, ds);

    // 2) P1' = round_tf32( ds ∘ (x @ W1) )   [32768,256]@[256,512]
    gemm_tf32_kernel<false, false, true, false, true>
        <<<dim3(HIDC / 256, (BATCH * NNODE) / 128, 1), 512, SMEM_BYTES>>>(
            x, W1, P1, ds, nullptr,
            BATCH * NNODE, HIDC, INC, 0, 0, 0, 0);

    // 3) H = relu( ds ∘ (A @ P1' + P1') + b1 )   per batch 4096x4096 @ 4096x512
    gemm_tf32_kernel<true, true, false, true, false>
        <<<dim3(HIDC / 256, NNODE / 128, BATCH), 512, SMEM_BYTES>>>(
            A, P1, H, ds, b1,
            NNODE, HIDC, NNODE,
            (long long)NNODE * NNODE, (long long)NNODE * HIDC,
            (long long)NNODE * HIDC, NNODE);

    // 4) P2' = round_tf32( ds ∘ (H @ W2) )   [32768,512]@[512,256]
    gemm_tf32_kernel<false, false, true, false, true>
        <<<dim3(OUTC / 256, (BATCH * NNODE) / 128, 1), 512, SMEM_BYTES>>>(
            H, W2, P2, ds, nullptr,
            BATCH * NNODE, OUTC, HIDC, 0, 0, 0, 0);

    // 5) out = ds ∘ (A @ P2' + P2') + b2
    gemm_tf32_kernel<true, false, false, true, false>
        <<<dim3(OUTC / 256, NNODE / 128, BATCH), 512, SMEM_BYTES>>>(
            A, P2, out, ds, b2,
            NNODE, OUTC, NNODE,
            (long long)NNODE * NNODE, (long long)NNODE * OUTC,
            (long long)NNODE * OUTC, NNODE);
}

// round 5
// speedup vs baseline: 1.6967x; 1.6967x over previous
#include <cuda_runtime.h>
#include <cuda_fp16.h>
#include <cstdint>

// ---------------------------------------------------------------------------
// GraphEncoder on GB300 (sm_103a) — fp16 mma.sync pipeline (tcgen05 blocked by
// harness PTX target sm_103 without 'a').
//
//   ds[i] = rsqrt(1 + rowsum(A)[i]);   xs = ds∘x  (fp16)
//   Z1  = ds∘(A@xs + xs)                     (agg, N=256)   [= nrm@x]
//   H   = relu(Z1@W1 + b1)                   (feature)
//   P2  = ds∘(H@W2)                          (feature)
//   out = ds∘(A@P2 + P2) + b2                (agg, N=256)
//
// All GEMM operands stored fp16, K-major, with K pre-permuted pairwise
// (pair order 0,4,1,5,2,6,3,7 within 16-half groups) so fragment fetches are
// LDS.64 with minimal bank phases. CTA 128x128, 4 warps of 64x64, BK=64,
// 3-stage cp.async, SW128 chunk swizzle.
// ---------------------------------------------------------------------------

#define DEV_INLINE __device__ __forceinline__

static constexpr int BATCH = 8, NNODE = 4096, INC = 256, HIDC = 512, OUTC = 256;
static constexpr int MT = BATCH * NNODE;   // 32768

// Scratch (allocation-free __device__ globals)
__device__ float  g_ds [MT];                                     // 128 KB
__device__ __half g_Ar [(size_t)BATCH * NNODE * NNODE];          // 256 MB
__device__ __half g_xs [(size_t)MT * INC];                       // 16 MB (plain)
__device__ __half g_xst[(size_t)BATCH * INC * NNODE];            // 16 MB (T, interleaved)
__device__ __half g_Z1 [(size_t)MT * INC];                       // 16 MB (interleaved)
__device__ __half g_H  [(size_t)MT * HIDC];                      // 32 MB (interleaved)
__device__ __half g_P2t[(size_t)BATCH * OUTC * NNODE];           // 16 MB (T, interleaved)
__device__ __half g_P2 [(size_t)MT * OUTC];                      // 16 MB (plain)
__device__ __half g_W1t[HIDC * INC];                             // 256 KB
__device__ __half g_W2t[OUTC * HIDC];                            // 256 KB

// ---------------------------------------------------------------------------
// helpers
// ---------------------------------------------------------------------------
DEV_INLINE int pos8(int p) { return ((p & 3) << 1) | ((p >> 2) & 1); }

DEV_INLINE void cp_async16(uint32_t saddr, const void* gmem) {
    asm volatile("cp.async.cg.shared.global [%0], [%1], 16;" :: "r"(saddr), "l"(gmem));
}
DEV_INLINE void cp_commit() { asm volatile("cp.async.commit_group;"); }
template <int N> DEV_INLINE void cp_wait() { asm volatile("cp.async.wait_group %0;" :: "n"(N)); }

DEV_INLINE uint32_t smem_u32(const void* p) {
    return (uint32_t)__cvta_generic_to_shared(p);
}

DEV_INLINE void lds64(uint32_t& x, uint32_t& y, uint32_t addr) {
    asm volatile("ld.shared.v2.b32 {%0, %1}, [%2];" : "=r"(x), "=r"(y) : "r"(addr));
}

DEV_INLINE void mma_f16(float* d, const uint32_t* a, const uint32_t* b) {
    asm volatile(
        "mma.sync.aligned.m16n8k16.row.col.f32.f16.f16.f32 "
        "{%0,%1,%2,%3},{%4,%5,%6,%7},{%8,%9},{%0,%1,%2,%3};"
        : "+f"(d[0]), "+f"(d[1]), "+f"(d[2]), "+f"(d[3])
        : "r"(a[0]), "r"(a[1]), "r"(a[2]), "r"(a[3]), "r"(b[0]), "r"(b[1]));
}

// ---------------------------------------------------------------------------
// prep_A: ds[row] = rsqrt(1+rowsum), Ar = fp16(A) pair-interleaved K-major
// one block (256 thr) per row
// ---------------------------------------------------------------------------
__global__ void __launch_bounds__(256) prep_A_kernel(const float* __restrict__ A,
                                                     __half* __restrict__ Ar,
                                                     float* __restrict__ ds) {
    __shared__ float srow[NNODE];
    long long row = blockIdx.x;
    const float4* p = (const float4*)(A + row * (long long)NNODE);
    float s = 0.f;
    #pragma unroll 2
    for (int i = threadIdx.x; i < NNODE / 4; i += 256) {
        float4 v = p[i];
        s += (v.x + v.y) + (v.z + v.w);
        *(float4*)(srow + 4 * i) = v;
    }
    #pragma unroll
    for (int o = 16; o; o >>= 1) s += __shfl_xor_sync(0xFFFFFFFFu, s, o);
    __shared__ float ws[8];
    if ((threadIdx.x & 31) == 0) ws[threadIdx.x >> 5] = s;
    __syncthreads();
    if (threadIdx.x == 0) {
        float tot = 0.f;
        #pragma unroll
        for (int i = 0; i < 8; i++) tot += ws[i];
        ds[row] = rsqrtf(tot + 1.0f);
    }
    // interleaved fp16 write: group g = 16 halfs, pair order (0,4,1,5,2,6,3,7)
    int g = threadIdx.x;                  // 256 groups
    const float* src = srow + 16 * g;
    __half2 ph[8];
    #pragma unroll
    for (int pp = 0; pp < 8; pp++)
        ph[pos8(pp)] = __floats2half2_rn(src[2 * pp], src[2 * pp + 1]);
    uint4* dst = (uint4*)(Ar + row * (long long)NNODE + 16 * g);
    dst[0] = *(uint4*)&ph[0];
    dst[1] = *(uint4*)&ph[4];
}

// ---------------------------------------------------------------------------
// prep_x: xs = fp16(ds∘x) plain row-major; xst = transposed, pair-interleaved
// tile 32 nodes x 32 ch, 256 threads
// ---------------------------------------------------------------------------
__global__ void __launch_bounds__(256) prep_x_kernel(const float* __restrict__ x,
                                                     const float* __restrict__ ds,
                                                     __half* __restrict__ xs,
                                                     __half* __restrict__ xst) {
    __shared__ __half sm[32][34];
    int m0 = blockIdx.x * 32, c0 = blockIdx.y * 32, b = blockIdx.z;
    #pragma unroll
    for (int r4 = 0; r4 < 4; r4++) {
        int idx = threadIdx.x + r4 * 256;
        int im = idx >> 5, ic = idx & 31;
        long long gm = (long long)b * NNODE + m0 + im;
        float v = x[gm * INC + c0 + ic] * ds[gm];
        __half h = __float2half_rn(v);
        sm[im][ic] = h;
        xs[gm * INC + c0 + ic] = h;
    }
    __syncthreads();
    #pragma unroll
    for (int r2 = 0; r2 < 2; r2++) {
        int pidx = threadIdx.x + r2 * 256;   // 512 = 32 ch * 16 pairs
        int jc = pidx >> 4, lp = pidx & 15;
        int grp = lp >> 3, pp = lp & 7;
        int mA = grp * 16 + 2 * pp;
        __half2 hv = __halves2half2(sm[mA][jc], sm[mA + 1][jc]);
        long long dst = (long long)b * INC * NNODE + (long long)(c0 + jc) * NNODE
                      + m0 + grp * 16 + pos8(pp) * 2;
        *(__half2*)(xst + dst) = hv;
    }
}

// ---------------------------------------------------------------------------
// prep_W: Wt[n][k-interleaved] = fp16(W[k][n]),  one thread per output pair
// ---------------------------------------------------------------------------
__global__ void __launch_bounds__(256) prep_W_kernel(const float* __restrict__ W,
                                                     __half* __restrict__ Wt,
                                                     int K, int N) {
    int id = blockIdx.x * 256 + threadIdx.x;
    if (id >= N * (K / 2)) return;
    int n = id / (K / 2), pk = id % (K / 2);
    int grp = pk >> 3, pp = pk & 7;
    int k = 2 * pk;
    __half2 hv = __floats2half2_rn(W[(long long)k * N + n], W[(long long)(k + 1) * N + n]);
    *(__half2*)(Wt + (long long)n * K + grp * 16 + pos8(pp) * 2) = hv;
}

// ---------------------------------------------------------------------------
// fp16 GEMM: C = A(MxK, K-major interleaved) @ B(NxK, K-major interleaved)^T
// CTA 128x128, 4 warps (2x2 of 64x64), BK=64, 3-stage cp.async, SW128 swizzle.
//
// EPI 0 (G1): Z1[m][n] = ds[m]*(acc + xs[m][n])          -> half, interleaved cols
// EPI 1 (G2): H[m][n]  = relu(acc + bias[n])             -> half, interleaved cols
// EPI 2 (G3): P2t[n][m] = ds[m]*acc (transposed+intlv) ; P2[m][n] plain copy
// EPI 3 (G4): out[m][n] = ds[m]*(acc + P2[m][n]) + bias[n]   -> fp32 plain
// ---------------------------------------------------------------------------
static constexpr int STAGE_BYTES = 32768;                  // A 16KB + B 16KB
static constexpr int SMEM_BYTES = 3 * STAGE_BYTES;         // 96 KB

template <int EPI>
__global__ void __launch_bounds__(128, 2) gemm_f16(
    const __half* __restrict__ Ag, const __half* __restrict__ Bg, void* __restrict__ Cg,
    const __half* __restrict__ selfg, const float* __restrict__ ds,
    const float* __restrict__ bias, __half* __restrict__ C2g,
    int K, long long lda, long long ldb, long long ldc, long long ldself,
    long long sAb, long long sBb, long long sCb, long long sSelfb, int dsStride) {

    extern __shared__ char smem[];
    const uint32_t sbase = smem_u32(smem);

    const int tid = threadIdx.x;
    const int b = blockIdx.z;
    const long long m0 = (long long)blockIdx.y * 128;
    const int n0 = blockIdx.x * 128;

    const __half* Ab = Ag + (long long)b * sAb;
    const __half* Bb = Bg + (long long)b * sBb;

    const int warp = tid >> 5, lane = tid & 31;
    const int gr = lane >> 2, t = lane & 3;
    const int mW = (warp >> 1) * 64, nW = (warp & 1) * 64;

    float acc[4][8][4];
    #pragma unroll
    for (int mi = 0; mi < 4; mi++)
        #pragma unroll
        for (int ni = 0; ni < 8; ni++)
            #pragma unroll
            for (int e = 0; e < 4; e++) acc[mi][ni][e] = 0.f;

    auto load_tile = [&](int st, int kt) {
        uint32_t sa = sbase + st * STAGE_BYTES;
        #pragma unroll
        for (int i = 0; i < 8; i++) {
            int cq = tid + i * 128;
            int r = cq >> 3, c = cq & 7;
            const __half* g = Ab + (m0 + r) * lda + kt + c * 8;
            cp_async16(sa + r * 128 + ((c ^ (r & 7)) << 4), g);
        }
        uint32_t sb = sa + 16384;
        #pragma unroll
        for (int i = 0; i < 8; i++) {
            int cq = tid + i * 128;
            int r = cq >> 3, c = cq & 7;
            const __half* g = Bb + (long long)(n0 + r) * ldb + kt + c * 8;
            cp_async16(sb + r * 128 + ((c ^ (r & 7)) << 4), g);
        }
    };

    const int nK = K / 64;
    load_tile(0, 0); cp_commit();
    if (nK > 1) { load_tile(1, 64); cp_commit(); }

    int stage = 0;
    for (int tt = 0; tt < nK; tt++) {
        if (tt + 2 < nK) cp_wait<1>(); else cp_wait<0>();
        __syncthreads();
        if (tt + 2 < nK) { load_tile((tt + 2) % 3, (tt + 2) * 64); cp_commit(); }

        uint32_t sa = sbase + stage * STAGE_BYTES;
        uint32_t sb = sa + 16384;

        #pragma unroll
        for (int G = 0; G < 4; G++) {
            const int chunk = (G << 1) | (t >> 1);
            const uint32_t swo = ((chunk ^ gr) << 4) + ((t & 1) << 3);
            uint32_t a[4][4], bf[8][2];
            #pragma unroll
            for (int mi = 0; mi < 4; mi++) {
                uint32_t ra = sa + (mW + mi * 16 + gr) * 128 + swo;
                lds64(a[mi][0], a[mi][2], ra);
                lds64(a[mi][1], a[mi][3], ra + 1024);
            }
            #pragma unroll
            for (int ni = 0; ni < 8; ni++) {
                uint32_t rb = sb + (nW + ni * 8 + gr) * 128 + swo;
                lds64(bf[ni][0], bf[ni][1], rb);
            }
            #pragma unroll
            for (int mi = 0; mi < 4; mi++)
                #pragma unroll
                for (int ni = 0; ni < 8; ni++)
                    mma_f16(acc[mi][ni], a[mi], bf[ni]);
        }
        __syncthreads();
        stage = (stage + 1) % 3;
    }

    // ---------------- epilogue ----------------
    const __half* selfb = selfg + (long long)b * sSelfb;

    if (EPI == 2) {
        // transpose store: sT half[128][136], then per-n row writeout
        __half* sT = (__half*)smem;
        const long long gmb = (long long)blockIdx.y * 128;   // global m base
        #pragma unroll
        for (int mi = 0; mi < 4; mi++) {
            #pragma unroll
            for (int rr = 0; rr < 2; rr++) {
                int m_loc = mW + mi * 16 + gr + rr * 8;
                long long gm = gmb + m_loc;
                float d = ds[gm];
                #pragma unroll
                for (int ni = 0; ni < 8; ni++) {
                    int n_loc = nW + ni * 8 + 2 * t;
                    float v0 = d * acc[mi][ni][rr * 2 + 0];
                    float v1 = d * acc[mi][ni][rr * 2 + 1];
                    __half2 hv = __floats2half2_rn(v0, v1);
                    *(__half2*)(sT + m_loc * 136 + n_loc) = hv;
                    *(__half2*)(C2g + gm * ldc + n0 + n_loc) = hv;   // P2 plain copy
                }
            }
        }
        __syncthreads();
        // writeout: thread n = tid handles one output row of 128 m-halfs
        int bo = (int)(gmb >> 12);
        long long m0loc = gmb & 4095;
        __half* Ct = (__half*)Cg + (long long)bo * OUTC * NNODE
                   + (long long)(n0 + tid) * NNODE + m0loc;
        #pragma unroll
        for (int mg = 0; mg < 8; mg++) {
            __half2 ph[8];
            #pragma unroll
            for (int pp = 0; pp < 8; pp++) {
                int mA = mg * 16 + 2 * pp;
                ph[pos8(pp)] = __halves2half2(sT[mA * 136 + tid], sT[(mA + 1) * 136 + tid]);
            }
            uint4* dst = (uint4*)(Ct + mg * 16);
            dst[0] = *(uint4*)&ph[0];
            dst[1] = *(uint4*)&ph[4];
        }
        return;
    }

    #pragma unroll
    for (int mi = 0; mi < 4; mi++) {
        #pragma unroll
        for (int rr = 0; rr < 2; rr++) {
            int m_loc = mW + mi * 16 + gr + rr * 8;
            long long m = m0 + m_loc;
            float d = (EPI == 1) ? 1.f : ds[(long long)b * dsStride + m];
            #pragma unroll
            for (int ni = 0; ni < 8; ni++) {
                int col = n0 + nW + ni * 8 + 2 * t;
                float v0 = acc[mi][ni][rr * 2 + 0];
                float v1 = acc[mi][ni][rr * 2 + 1];
                if (EPI == 0) {
                    float2 sv = __half22float2(*(const __half2*)(selfb + m * ldself + col));
                    v0 = d * (v0 + sv.x);
                    v1 = d * (v1 + sv.y);
                } else if (EPI == 1) {
                    v0 = fmaxf(v0 + bias[col], 0.f);
                    v1 = fmaxf(v1 + bias[col + 1], 0.f);
                } else {  // EPI == 3
                    float2 sv = __half22float2(*(const __half2*)(selfb + m * ldself + col));
                    v0 = fmaf(d, v0 + sv.x, bias[col]);
                    v1 = fmaf(d, v1 + sv.y, bias[col + 1]);
                }
                if (EPI == 3) {
                    float* Cf = (float*)Cg + (long long)b * sCb;
                    *(float2*)(Cf + m * ldc + col) = make_float2(v0, v1);
                } else {
                    // interleaved half store: pair position within 16-col group
                    int g16 = col >> 4, lp = (col >> 1) & 7;
                    __half* Ch = (__half*)Cg + (long long)b * sCb;
                    *(__half2*)(Ch + m * ldc + (g16 << 4) + (pos8(lp) << 1)) =
                        __floats2half2_rn(v0, v1);
                }
            }
        }
    }
}

// ---------------------------------------------------------------------------
// launch
// ---------------------------------------------------------------------------
extern "C" void kernel_launch(void* const* d_in, const int* in_sizes, int n_in,
                              void* d_out, int out_size) {
    const float* x  = (const float*)d_in[0];   // [8,4096,256]
    const float* A  = (const float*)d_in[1];   // [8,4096,4096]
    const float* W1 = (const float*)d_in[2];   // [256,512]
    const float* b1 = (const float*)d_in[3];   // [512]
    const float* W2 = (const float*)d_in[4];   // [512,256]
    const float* b2 = (const float*)d_in[5];   // [256]
    float* out = (float*)d_out;                // [8,4096,256]

    float* ds;
    __half *Ar, *xs, *xst, *Z1, *H, *P2t, *P2, *W1t, *W2t;
    cudaGetSymbolAddress((void**)&ds,  g_ds);
    cudaGetSymbolAddress((void**)&Ar,  g_Ar);
    cudaGetSymbolAddress((void**)&xs,  g_xs);
    cudaGetSymbolAddress((void**)&xst, g_xst);
    cudaGetSymbolAddress((void**)&Z1,  g_Z1);
    cudaGetSymbolAddress((void**)&H,   g_H);
    cudaGetSymbolAddress((void**)&P2t, g_P2t);
    cudaGetSymbolAddress((void**)&P2,  g_P2);
    cudaGetSymbolAddress((void**)&W1t, g_W1t);
    cudaGetSymbolAddress((void**)&W2t, g_W2t);

    cudaFuncSetAttribute(gemm_f16<0>, cudaFuncAttributeMaxDynamicSharedMemorySize, SMEM_BYTES);
    cudaFuncSetAttribute(gemm_f16<1>, cudaFuncAttributeMaxDynamicSharedMemorySize, SMEM_BYTES);
    cudaFuncSetAttribute(gemm_f16<2>, cudaFuncAttributeMaxDynamicSharedMemorySize, SMEM_BYTES);
    cudaFuncSetAttribute(gemm_f16<3>, cudaFuncAttributeMaxDynamicSharedMemorySize, SMEM_BYTES);

    // prep
    prep_A_kernel<<<BATCH * NNODE, 256>>>(A, Ar, ds);
    prep_x_kernel<<<dim3(NNODE / 32, INC / 32, BATCH), 256>>>(x, ds, xs, xst);
    prep_W_kernel<<<(HIDC * (INC / 2) + 255) / 256, 256>>>(W1, W1t, INC, HIDC);
    prep_W_kernel<<<(OUTC * (HIDC / 2) + 255) / 256, 256>>>(W2, W2t, HIDC, OUTC);

    // G1: Z1 = ds∘(A@xs + xs)   (agg, per-batch, N=256)
    gemm_f16<0><<<dim3(INC / 128, NNODE / 128, BATCH), 128, SMEM_BYTES>>>(
        Ar, xst, Z1, xs, ds, nullptr, nullptr,
        NNODE, NNODE, NNODE, INC, INC,
        (long long)NNODE * NNODE, (long long)INC * NNODE,
        (long long)NNODE * INC, (long long)NNODE * INC, NNODE);

    // G2: H = relu(Z1@W1 + b1)   (feature, M=32768, N=512, K=256)
    gemm_f16<1><<<dim3(HIDC / 128, MT / 128, 1), 128, SMEM_BYTES>>>(
        Z1, W1t, H, nullptr, ds, b1, nullptr,
        INC, INC, INC, HIDC, 0, 0, 0, 0, 0, 0);

    // G3: P2t = (ds∘(H@W2))^T  + P2 plain copy   (feature, N=256, K=512)
    gemm_f16<2><<<dim3(OUTC / 128, MT / 128, 1), 128, SMEM_BYTES>>>(
        H, W2t, P2t, nullptr, ds, nullptr, P2,
        HIDC, HIDC, HIDC, OUTC, 0, 0, 0, 0, 0, 0);

    // G4: out = ds∘(A@P2 + P2) + b2   (agg, per-batch, N=256)
    gemm_f16<3><<<dim3(OUTC / 128, NNODE / 128, BATCH), 128, SMEM_BYTES>>>(
        Ar, P2t, out, P2, ds, b2, nullptr,
        NNODE, NNODE, NNODE, OUTC, OUTC,
        (long long)NNODE * NNODE, (long long)OUTC * NNODE,
        (long long)NNODE * OUTC, (long long)NNODE * OUTC, NNODE);
}

// round 6
// speedup vs baseline: 1.7958x; 1.0584x over previous
#include <cuda_runtime.h>
#include <cuda_fp16.h>
#include <cstdint>

// ---------------------------------------------------------------------------
// GraphEncoder on GB300 (sm_103a) — fp16 mma.sync pipeline.
//
//   ds[i] = rsqrt(1 + rowsum(A)[i]);   xs = ds∘x  (fp16)
//   Z1  = ds∘(A@xs + xs)                     (agg, N=256)   [= nrm@x]
//   H   = relu(Z1@W1 + b1)                   (feature)
//   P2  = ds∘(H@W2)                          (feature)
//   out = ds∘(A@P2 + P2) + b2                (agg, N=256)
//
// R5: 3 CTAs/SM (launch_bounds(128,3)), 2-stage cp.async ring, register-lean
// hot loop (A frags resident, B streamed 1 lds64 -> 4 MMA).
// ---------------------------------------------------------------------------

#define DEV_INLINE __device__ __forceinline__

static constexpr int BATCH = 8, NNODE = 4096, INC = 256, HIDC = 512, OUTC = 256;
static constexpr int MT = BATCH * NNODE;   // 32768

// Scratch (allocation-free __device__ globals)
__device__ float  g_ds [MT];                                     // 128 KB
__device__ __half g_Ar [(size_t)BATCH * NNODE * NNODE];          // 256 MB
__device__ __half g_xs [(size_t)MT * INC];                       // 16 MB (plain)
__device__ __half g_xst[(size_t)BATCH * INC * NNODE];            // 16 MB (T, interleaved)
__device__ __half g_Z1 [(size_t)MT * INC];                       // 16 MB (interleaved)
__device__ __half g_H  [(size_t)MT * HIDC];                      // 32 MB (interleaved)
__device__ __half g_P2t[(size_t)BATCH * OUTC * NNODE];           // 16 MB (T, interleaved)
__device__ __half g_P2 [(size_t)MT * OUTC];                      // 16 MB (plain)
__device__ __half g_W1t[HIDC * INC];                             // 256 KB
__device__ __half g_W2t[OUTC * HIDC];                            // 256 KB

// ---------------------------------------------------------------------------
// helpers
// ---------------------------------------------------------------------------
DEV_INLINE int pos8(int p) { return ((p & 3) << 1) | ((p >> 2) & 1); }

DEV_INLINE void cp_async16(uint32_t saddr, const void* gmem) {
    asm volatile("cp.async.cg.shared.global [%0], [%1], 16;" :: "r"(saddr), "l"(gmem));
}
DEV_INLINE void cp_commit() { asm volatile("cp.async.commit_group;"); }
template <int N> DEV_INLINE void cp_wait() { asm volatile("cp.async.wait_group %0;" :: "n"(N)); }

DEV_INLINE uint32_t smem_u32(const void* p) {
    return (uint32_t)__cvta_generic_to_shared(p);
}

DEV_INLINE void lds64(uint32_t& x, uint32_t& y, uint32_t addr) {
    asm volatile("ld.shared.v2.b32 {%0, %1}, [%2];" : "=r"(x), "=r"(y) : "r"(addr));
}

DEV_INLINE void mma_f16(float* d, const uint32_t* a, const uint32_t* b) {
    asm volatile(
        "mma.sync.aligned.m16n8k16.row.col.f32.f16.f16.f32 "
        "{%0,%1,%2,%3},{%4,%5,%6,%7},{%8,%9},{%0,%1,%2,%3};"
        : "+f"(d[0]), "+f"(d[1]), "+f"(d[2]), "+f"(d[3])
        : "r"(a[0]), "r"(a[1]), "r"(a[2]), "r"(a[3]), "r"(b[0]), "r"(b[1]));
}

// ---------------------------------------------------------------------------
// prep_A: ds[row] = rsqrt(1+rowsum), Ar = fp16(A) pair-interleaved K-major
// one block (256 thr) per row
// ---------------------------------------------------------------------------
__global__ void __launch_bounds__(256) prep_A_kernel(const float* __restrict__ A,
                                                     __half* __restrict__ Ar,
                                                     float* __restrict__ ds) {
    __shared__ float srow[NNODE];
    long long row = blockIdx.x;
    const float4* p = (const float4*)(A + row * (long long)NNODE);
    float s = 0.f;
    #pragma unroll 2
    for (int i = threadIdx.x; i < NNODE / 4; i += 256) {
        float4 v = p[i];
        s += (v.x + v.y) + (v.z + v.w);
        *(float4*)(srow + 4 * i) = v;
    }
    #pragma unroll
    for (int o = 16; o; o >>= 1) s += __shfl_xor_sync(0xFFFFFFFFu, s, o);
    __shared__ float ws[8];
    if ((threadIdx.x & 31) == 0) ws[threadIdx.x >> 5] = s;
    __syncthreads();
    if (threadIdx.x == 0) {
        float tot = 0.f;
        #pragma unroll
        for (int i = 0; i < 8; i++) tot += ws[i];
        ds[row] = rsqrtf(tot + 1.0f);
    }
    // interleaved fp16 write: group g = 16 halfs, pair order (0,4,1,5,2,6,3,7)
    int g = threadIdx.x;                  // 256 groups
    const float* src = srow + 16 * g;
    __half2 ph[8];
    #pragma unroll
    for (int pp = 0; pp < 8; pp++)
        ph[pos8(pp)] = __floats2half2_rn(src[2 * pp], src[2 * pp + 1]);
    uint4* dst = (uint4*)(Ar + row * (long long)NNODE + 16 * g);
    dst[0] = *(uint4*)&ph[0];
    dst[1] = *(uint4*)&ph[4];
}

// ---------------------------------------------------------------------------
// prep_x: xs = fp16(ds∘x) plain row-major; xst = transposed, pair-interleaved
// tile 32 nodes x 32 ch, 256 threads
// ---------------------------------------------------------------------------
__global__ void __launch_bounds__(256) prep_x_kernel(const float* __restrict__ x,
                                                     const float* __restrict__ ds,
                                                     __half* __restrict__ xs,
                                                     __half* __restrict__ xst) {
    __shared__ __half sm[32][34];
    int m0 = blockIdx.x * 32, c0 = blockIdx.y * 32, b = blockIdx.z;
    #pragma unroll
    for (int r4 = 0; r4 < 4; r4++) {
        int idx = threadIdx.x + r4 * 256;
        int im = idx >> 5, ic = idx & 31;
        long long gm = (long long)b * NNODE + m0 + im;
        float v = x[gm * INC + c0 + ic] * ds[gm];
        __half h = __float2half_rn(v);
        sm[im][ic] = h;
        xs[gm * INC + c0 + ic] = h;
    }
    __syncthreads();
    #pragma unroll
    for (int r2 = 0; r2 < 2; r2++) {
        int pidx = threadIdx.x + r2 * 256;   // 512 = 32 ch * 16 pairs
        int jc = pidx >> 4, lp = pidx & 15;
        int grp = lp >> 3, pp = lp & 7;
        int mA = grp * 16 + 2 * pp;
        __half2 hv = __halves2half2(sm[mA][jc], sm[mA + 1][jc]);
        long long dst = (long long)b * INC * NNODE + (long long)(c0 + jc) * NNODE
                      + m0 + grp * 16 + pos8(pp) * 2;
        *(__half2*)(xst + dst) = hv;
    }
}

// ---------------------------------------------------------------------------
// prep_W: Wt[n][k-interleaved] = fp16(W[k][n]),  one thread per output pair
// ---------------------------------------------------------------------------
__global__ void __launch_bounds__(256) prep_W_kernel(const float* __restrict__ W,
                                                     __half* __restrict__ Wt,
                                                     int K, int N) {
    int id = blockIdx.x * 256 + threadIdx.x;
    if (id >= N * (K / 2)) return;
    int n = id / (K / 2), pk = id % (K / 2);
    int grp = pk >> 3, pp = pk & 7;
    int k = 2 * pk;
    __half2 hv = __floats2half2_rn(W[(long long)k * N + n], W[(long long)(k + 1) * N + n]);
    *(__half2*)(Wt + (long long)n * K + grp * 16 + pos8(pp) * 2) = hv;
}

// ---------------------------------------------------------------------------
// fp16 GEMM: C = A(MxK, K-major interleaved) @ B(NxK, K-major interleaved)^T
// CTA 128x128, 4 warps (2x2 of 64x64), BK=64, 2-stage cp.async, 3 CTAs/SM.
//
// EPI 0 (G1): Z1[m][n] = ds[m]*(acc + xs[m][n])          -> half, interleaved cols
// EPI 1 (G2): H[m][n]  = relu(acc + bias[n])             -> half, interleaved cols
// EPI 2 (G3): P2t[n][m] = ds[m]*acc (transposed+intlv) ; P2[m][n] plain copy
// EPI 3 (G4): out[m][n] = ds[m]*(acc + P2[m][n]) + bias[n]   -> fp32 plain
// ---------------------------------------------------------------------------
static constexpr int STAGE_BYTES = 32768;                  // A 16KB + B 16KB
static constexpr int SMEM_BYTES = 2 * STAGE_BYTES;         // 64 KB

template <int EPI>
__global__ void __launch_bounds__(128, 3) gemm_f16(
    const __half* __restrict__ Ag, const __half* __restrict__ Bg, void* __restrict__ Cg,
    const __half* __restrict__ selfg, const float* __restrict__ ds,
    const float* __restrict__ bias, __half* __restrict__ C2g,
    int K, long long lda, long long ldb, long long ldc, long long ldself,
    long long sAb, long long sBb, long long sCb, long long sSelfb, int dsStride) {

    extern __shared__ char smem[];
    const uint32_t sbase = smem_u32(smem);

    const int tid = threadIdx.x;
    const int b = blockIdx.z;
    const long long m0 = (long long)blockIdx.y * 128;
    const int n0 = blockIdx.x * 128;

    const __half* Ab = Ag + (long long)b * sAb;
    const __half* Bb = Bg + (long long)b * sBb;

    const int warp = tid >> 5, lane = tid & 31;
    const int gr = lane >> 2, t = lane & 3;
    const int mW = (warp >> 1) * 64, nW = (warp & 1) * 64;

    float acc[4][8][4];
    #pragma unroll
    for (int mi = 0; mi < 4; mi++)
        #pragma unroll
        for (int ni = 0; ni < 8; ni++)
            #pragma unroll
            for (int e = 0; e < 4; e++) acc[mi][ni][e] = 0.f;

    auto load_tile = [&](int st, int kt) {
        uint32_t sa = sbase + st * STAGE_BYTES;
        #pragma unroll
        for (int i = 0; i < 8; i++) {
            int cq = tid + i * 128;
            int r = cq >> 3, c = cq & 7;
            const __half* g = Ab + (m0 + r) * lda + kt + c * 8;
            cp_async16(sa + r * 128 + ((c ^ (r & 7)) << 4), g);
        }
        uint32_t sb = sa + 16384;
        #pragma unroll
        for (int i = 0; i < 8; i++) {
            int cq = tid + i * 128;
            int r = cq >> 3, c = cq & 7;
            const __half* g = Bb + (long long)(n0 + r) * ldb + kt + c * 8;
            cp_async16(sb + r * 128 + ((c ^ (r & 7)) << 4), g);
        }
    };

    const int nK = K / 64;
    load_tile(0, 0); cp_commit();

    for (int tt = 0; tt < nK; tt++) {
        if (tt + 1 < nK) { load_tile((tt + 1) & 1, (tt + 1) * 64); cp_commit(); cp_wait<1>(); }
        else cp_wait<0>();
        __syncthreads();

        uint32_t sa = sbase + (tt & 1) * STAGE_BYTES;
        uint32_t sb = sa + 16384;

        #pragma unroll
        for (int G = 0; G < 4; G++) {
            const int chunk = (G << 1) | (t >> 1);
            const uint32_t swo = ((chunk ^ gr) << 4) + ((t & 1) << 3);
            uint32_t a[4][4];
            #pragma unroll
            for (int mi = 0; mi < 4; mi++) {
                uint32_t ra = sa + (mW + mi * 16 + gr) * 128 + swo;
                lds64(a[mi][0], a[mi][2], ra);
                lds64(a[mi][1], a[mi][3], ra + 1024);
            }
            #pragma unroll
            for (int ni = 0; ni < 8; ni++) {
                uint32_t bf[2];
                lds64(bf[0], bf[1], sb + (nW + ni * 8 + gr) * 128 + swo);
                #pragma unroll
                for (int mi = 0; mi < 4; mi++)
                    mma_f16(acc[mi][ni], a[mi], bf);
            }
        }
        __syncthreads();
    }

    // ---------------- epilogue ----------------
    const __half* selfb = selfg + (long long)b * sSelfb;

    if (EPI == 2) {
        // transpose store: sT half[128][136], then per-n row writeout
        __half* sT = (__half*)smem;
        const long long gmb = (long long)blockIdx.y * 128;   // global m base
        #pragma unroll
        for (int mi = 0; mi < 4; mi++) {
            #pragma unroll
            for (int rr = 0; rr < 2; rr++) {
                int m_loc = mW + mi * 16 + gr + rr * 8;
                long long gm = gmb + m_loc;
                float d = ds[gm];
                #pragma unroll
                for (int ni = 0; ni < 8; ni++) {
                    int n_loc = nW + ni * 8 + 2 * t;
                    float v0 = d * acc[mi][ni][rr * 2 + 0];
                    float v1 = d * acc[mi][ni][rr * 2 + 1];
                    __half2 hv = __floats2half2_rn(v0, v1);
                    *(__half2*)(sT + m_loc * 136 + n_loc) = hv;
                    *(__half2*)(C2g + gm * ldc + n0 + n_loc) = hv;   // P2 plain copy
                }
            }
        }
        __syncthreads();
        // writeout: thread n = tid handles one output row of 128 m-halfs
        int bo = (int)(gmb >> 12);
        long long m0loc = gmb & 4095;
        __half* Ct = (__half*)Cg + (long long)bo * OUTC * NNODE
                   + (long long)(n0 + tid) * NNODE + m0loc;
        #pragma unroll
        for (int mg = 0; mg < 8; mg++) {
            __half2 ph[8];
            #pragma unroll
            for (int pp = 0; pp < 8; pp++) {
                int mA = mg * 16 + 2 * pp;
                ph[pos8(pp)] = __halves2half2(sT[mA * 136 + tid], sT[(mA + 1) * 136 + tid]);
            }
            uint4* dst = (uint4*)(Ct + mg * 16);
            dst[0] = *(uint4*)&ph[0];
            dst[1] = *(uint4*)&ph[4];
        }
        return;
    }

    #pragma unroll
    for (int mi = 0; mi < 4; mi++) {
        #pragma unroll
        for (int rr = 0; rr < 2; rr++) {
            int m_loc = mW + mi * 16 + gr + rr * 8;
            long long m = m0 + m_loc;
            float d = (EPI == 1) ? 1.f : ds[(long long)b * dsStride + m];
            #pragma unroll
            for (int ni = 0; ni < 8; ni++) {
                int col = n0 + nW + ni * 8 + 2 * t;
                float v0 = acc[mi][ni][rr * 2 + 0];
                float v1 = acc[mi][ni][rr * 2 + 1];
                if (EPI == 0) {
                    float2 sv = __half22float2(*(const __half2*)(selfb + m * ldself + col));
                    v0 = d * (v0 + sv.x);
                    v1 = d * (v1 + sv.y);
                } else if (EPI == 1) {
                    v0 = fmaxf(v0 + bias[col], 0.f);
                    v1 = fmaxf(v1 + bias[col + 1], 0.f);
                } else {  // EPI == 3
                    float2 sv = __half22float2(*(const __half2*)(selfb + m * ldself + col));
                    v0 = fmaf(d, v0 + sv.x, bias[col]);
                    v1 = fmaf(d, v1 + sv.y, bias[col + 1]);
                }
                if (EPI == 3) {
                    float* Cf = (float*)Cg + (long long)b * sCb;
                    *(float2*)(Cf + m * ldc + col) = make_float2(v0, v1);
                } else {
                    // interleaved half store: pair position within 16-col group
                    int g16 = col >> 4, lp = (col >> 1) & 7;
                    __half* Ch = (__half*)Cg + (long long)b * sCb;
                    *(__half2*)(Ch + m * ldc + (g16 << 4) + (pos8(lp) << 1)) =
                        __floats2half2_rn(v0, v1);
                }
            }
        }
    }
}

// ---------------------------------------------------------------------------
// launch
// ---------------------------------------------------------------------------
extern "C" void kernel_launch(void* const* d_in, const int* in_sizes, int n_in,
                              void* d_out, int out_size) {
    const float* x  = (const float*)d_in[0];   // [8,4096,256]
    const float* A  = (const float*)d_in[1];   // [8,4096,4096]
    const float* W1 = (const float*)d_in[2];   // [256,512]
    const float* b1 = (const float*)d_in[3];   // [512]
    const float* W2 = (const float*)d_in[4];   // [512,256]
    const float* b2 = (const float*)d_in[5];   // [256]
    float* out = (float*)d_out;                // [8,4096,256]

    float* ds;
    __half *Ar, *xs, *xst, *Z1, *H, *P2t, *P2, *W1t, *W2t;
    cudaGetSymbolAddress((void**)&ds,  g_ds);
    cudaGetSymbolAddress((void**)&Ar,  g_Ar);
    cudaGetSymbolAddress((void**)&xs,  g_xs);
    cudaGetSymbolAddress((void**)&xst, g_xst);
    cudaGetSymbolAddress((void**)&Z1,  g_Z1);
    cudaGetSymbolAddress((void**)&H,   g_H);
    cudaGetSymbolAddress((void**)&P2t, g_P2t);
    cudaGetSymbolAddress((void**)&P2,  g_P2);
    cudaGetSymbolAddress((void**)&W1t, g_W1t);
    cudaGetSymbolAddress((void**)&W2t, g_W2t);

    cudaFuncSetAttribute(gemm_f16<0>, cudaFuncAttributeMaxDynamicSharedMemorySize, SMEM_BYTES);
    cudaFuncSetAttribute(gemm_f16<1>, cudaFuncAttributeMaxDynamicSharedMemorySize, SMEM_BYTES);
    cudaFuncSetAttribute(gemm_f16<2>, cudaFuncAttributeMaxDynamicSharedMemorySize, SMEM_BYTES);
    cudaFuncSetAttribute(gemm_f16<3>, cudaFuncAttributeMaxDynamicSharedMemorySize, SMEM_BYTES);

    // prep
    prep_A_kernel<<<BATCH * NNODE, 256>>>(A, Ar, ds);
    prep_x_kernel<<<dim3(NNODE / 32, INC / 32, BATCH), 256>>>(x, ds, xs, xst);
    prep_W_kernel<<<(HIDC * (INC / 2) + 255) / 256, 256>>>(W1, W1t, INC, HIDC);
    prep_W_kernel<<<(OUTC * (HIDC / 2) + 255) / 256, 256>>>(W2, W2t, HIDC, OUTC);

    // G1: Z1 = ds∘(A@xs + xs)   (agg, per-batch, N=256)
    gemm_f16<0><<<dim3(INC / 128, NNODE / 128, BATCH), 128, SMEM_BYTES>>>(
        Ar, xst, Z1, xs, ds, nullptr, nullptr,
        NNODE, NNODE, NNODE, INC, INC,
        (long long)NNODE * NNODE, (long long)INC * NNODE,
        (long long)NNODE * INC, (long long)NNODE * INC, NNODE);

    // G2: H = relu(Z1@W1 + b1)   (feature, M=32768, N=512, K=256)
    gemm_f16<1><<<dim3(HIDC / 128, MT / 128, 1), 128, SMEM_BYTES>>>(
        Z1, W1t, H, nullptr, ds, b1, nullptr,
        INC, INC, INC, HIDC, 0, 0, 0, 0, 0, 0);

    // G3: P2t = (ds∘(H@W2))^T  + P2 plain copy   (feature, N=256, K=512)
    gemm_f16<2><<<dim3(OUTC / 128, MT / 128, 1), 128, SMEM_BYTES>>>(
        H, W2t, P2t, nullptr, ds, nullptr, P2,
        HIDC, HIDC, HIDC, OUTC, 0, 0, 0, 0, 0, 0);

    // G4: out = ds∘(A@P2 + P2) + b2   (agg, per-batch, N=256)
    gemm_f16<3><<<dim3(OUTC / 128, NNODE / 128, BATCH), 128, SMEM_BYTES>>>(
        Ar, P2t, out, P2, ds, b2, nullptr,
        NNODE, NNODE, NNODE, OUTC, OUTC,
        (long long)NNODE * NNODE, (long long)OUTC * NNODE,
        (long long)NNODE * OUTC, (long long)NNODE * OUTC, NNODE);
}

// round 7
// speedup vs baseline: 2.3098x; 1.2863x over previous
#include <cuda_runtime.h>
#include <cuda_fp16.h>
#include <cstdint>

// ---------------------------------------------------------------------------
// GraphEncoder on GB300 (sm_103a) — fp16 mma.sync pipeline.
//
//   ds[i] = rsqrt(1 + rowsum(A)[i]);   xs = ds∘x  (fp16)
//   Z1  = ds∘(A@xs + xs)                     (agg, N=256)   [= nrm@x]
//   H   = relu(Z1@W1 + b1)                   (feature)
//   P2  = ds∘(H@W2)                          (feature)
//   out = ds∘(A@P2 + P2) + b2                (agg, N=256)
//
// R6: agg GEMMs use a wide occ-1 CTA (256 thr, 128x256 tile, 64x64 warp tile,
// BK=64, 4-stage 192KB ring, 1 barrier/iter). Feature GEMMs unchanged (R5).
// ---------------------------------------------------------------------------

#define DEV_INLINE __device__ __forceinline__

static constexpr int BATCH = 8, NNODE = 4096, INC = 256, HIDC = 512, OUTC = 256;
static constexpr int MT = BATCH * NNODE;   // 32768

// Scratch (allocation-free __device__ globals)
__device__ float  g_ds [MT];                                     // 128 KB
__device__ __half g_Ar [(size_t)BATCH * NNODE * NNODE];          // 256 MB
__device__ __half g_xs [(size_t)MT * INC];                       // 16 MB (plain)
__device__ __half g_xst[(size_t)BATCH * INC * NNODE];            // 16 MB (T, interleaved)
__device__ __half g_Z1 [(size_t)MT * INC];                       // 16 MB (interleaved)
__device__ __half g_H  [(size_t)MT * HIDC];                      // 32 MB (interleaved)
__device__ __half g_P2t[(size_t)BATCH * OUTC * NNODE];           // 16 MB (T, interleaved)
__device__ __half g_P2 [(size_t)MT * OUTC];                      // 16 MB (plain)
__device__ __half g_W1t[HIDC * INC];                             // 256 KB
__device__ __half g_W2t[OUTC * HIDC];                            // 256 KB

// ---------------------------------------------------------------------------
// helpers
// ---------------------------------------------------------------------------
DEV_INLINE int pos8(int p) { return ((p & 3) << 1) | ((p >> 2) & 1); }

DEV_INLINE void cp_async16(uint32_t saddr, const void* gmem) {
    asm volatile("cp.async.cg.shared.global [%0], [%1], 16;" :: "r"(saddr), "l"(gmem));
}
DEV_INLINE void cp_commit() { asm volatile("cp.async.commit_group;"); }
template <int N> DEV_INLINE void cp_wait() { asm volatile("cp.async.wait_group %0;" :: "n"(N)); }

DEV_INLINE uint32_t smem_u32(const void* p) {
    return (uint32_t)__cvta_generic_to_shared(p);
}

DEV_INLINE void lds64(uint32_t& x, uint32_t& y, uint32_t addr) {
    asm volatile("ld.shared.v2.b32 {%0, %1}, [%2];" : "=r"(x), "=r"(y) : "r"(addr));
}

DEV_INLINE void mma_f16(float* d, const uint32_t* a, const uint32_t* b) {
    asm volatile(
        "mma.sync.aligned.m16n8k16.row.col.f32.f16.f16.f32 "
        "{%0,%1,%2,%3},{%4,%5,%6,%7},{%8,%9},{%0,%1,%2,%3};"
        : "+f"(d[0]), "+f"(d[1]), "+f"(d[2]), "+f"(d[3])
        : "r"(a[0]), "r"(a[1]), "r"(a[2]), "r"(a[3]), "r"(b[0]), "r"(b[1]));
}

// ---------------------------------------------------------------------------
// prep_A: ds[row] = rsqrt(1+rowsum), Ar = fp16(A) pair-interleaved K-major
// ---------------------------------------------------------------------------
__global__ void __launch_bounds__(256) prep_A_kernel(const float* __restrict__ A,
                                                     __half* __restrict__ Ar,
                                                     float* __restrict__ ds) {
    __shared__ float srow[NNODE];
    long long row = blockIdx.x;
    const float4* p = (const float4*)(A + row * (long long)NNODE);
    float s = 0.f;
    #pragma unroll 2
    for (int i = threadIdx.x; i < NNODE / 4; i += 256) {
        float4 v = p[i];
        s += (v.x + v.y) + (v.z + v.w);
        *(float4*)(srow + 4 * i) = v;
    }
    #pragma unroll
    for (int o = 16; o; o >>= 1) s += __shfl_xor_sync(0xFFFFFFFFu, s, o);
    __shared__ float ws[8];
    if ((threadIdx.x & 31) == 0) ws[threadIdx.x >> 5] = s;
    __syncthreads();
    if (threadIdx.x == 0) {
        float tot = 0.f;
        #pragma unroll
        for (int i = 0; i < 8; i++) tot += ws[i];
        ds[row] = rsqrtf(tot + 1.0f);
    }
    int g = threadIdx.x;                  // 256 groups of 16 halfs
    const float* src = srow + 16 * g;
    __half2 ph[8];
    #pragma unroll
    for (int pp = 0; pp < 8; pp++)
        ph[pos8(pp)] = __floats2half2_rn(src[2 * pp], src[2 * pp + 1]);
    uint4* dst = (uint4*)(Ar + row * (long long)NNODE + 16 * g);
    dst[0] = *(uint4*)&ph[0];
    dst[1] = *(uint4*)&ph[4];
}

// ---------------------------------------------------------------------------
// prep_x: xs = fp16(ds∘x) plain row-major; xst = transposed, pair-interleaved
// ---------------------------------------------------------------------------
__global__ void __launch_bounds__(256) prep_x_kernel(const float* __restrict__ x,
                                                     const float* __restrict__ ds,
                                                     __half* __restrict__ xs,
                                                     __half* __restrict__ xst) {
    __shared__ __half sm[32][34];
    int m0 = blockIdx.x * 32, c0 = blockIdx.y * 32, b = blockIdx.z;
    #pragma unroll
    for (int r4 = 0; r4 < 4; r4++) {
        int idx = threadIdx.x + r4 * 256;
        int im = idx >> 5, ic = idx & 31;
        long long gm = (long long)b * NNODE + m0 + im;
        float v = x[gm * INC + c0 + ic] * ds[gm];
        __half h = __float2half_rn(v);
        sm[im][ic] = h;
        xs[gm * INC + c0 + ic] = h;
    }
    __syncthreads();
    #pragma unroll
    for (int r2 = 0; r2 < 2; r2++) {
        int pidx = threadIdx.x + r2 * 256;
        int jc = pidx >> 4, lp = pidx & 15;
        int grp = lp >> 3, pp = lp & 7;
        int mA = grp * 16 + 2 * pp;
        __half2 hv = __halves2half2(sm[mA][jc], sm[mA + 1][jc]);
        long long dst = (long long)b * INC * NNODE + (long long)(c0 + jc) * NNODE
                      + m0 + grp * 16 + pos8(pp) * 2;
        *(__half2*)(xst + dst) = hv;
    }
}

// ---------------------------------------------------------------------------
// prep_W: Wt[n][k-interleaved] = fp16(W[k][n])
// ---------------------------------------------------------------------------
__global__ void __launch_bounds__(256) prep_W_kernel(const float* __restrict__ W,
                                                     __half* __restrict__ Wt,
                                                     int K, int N) {
    int id = blockIdx.x * 256 + threadIdx.x;
    if (id >= N * (K / 2)) return;
    int n = id / (K / 2), pk = id % (K / 2);
    int grp = pk >> 3, pp = pk & 7;
    int k = 2 * pk;
    __half2 hv = __floats2half2_rn(W[(long long)k * N + n], W[(long long)(k + 1) * N + n]);
    *(__half2*)(Wt + (long long)n * K + grp * 16 + pos8(pp) * 2) = hv;
}

// ===========================================================================
// WIDE agg GEMM: C = A(MxK) @ B(NxK)^T, CTA 128x256, 8 warps of 64x64, BK=64,
// 4-stage ring (192KB), occ 1, 1 barrier per K-iter.
//   EPI 0: Z1[m][n] = ds[m]*(acc + self[m][n])      -> half interleaved
//   EPI 3: out[m][n] = ds[m]*(acc + self[m][n]) + bias[n]  -> fp32
// ===========================================================================
static constexpr int WSTAGE = 49152;                 // A 16KB + B 32KB
static constexpr int WSMEM  = 4 * WSTAGE;            // 192 KB

template <int EPI>
__global__ void __launch_bounds__(256, 1) gemm_f16_wide(
    const __half* __restrict__ Ag, const __half* __restrict__ Bg, void* __restrict__ Cg,
    const __half* __restrict__ selfg, const float* __restrict__ ds,
    const float* __restrict__ bias,
    int K, long long lda, long long ldb, long long ldc, long long ldself,
    long long sAb, long long sBb, long long sCb, long long sSelfb) {

    extern __shared__ char smem[];
    const uint32_t sbase = smem_u32(smem);

    const int tid = threadIdx.x;
    const int b = blockIdx.z;
    const long long m0 = (long long)blockIdx.y * 128;
    const int n0 = blockIdx.x * 256;

    const __half* Ab = Ag + (long long)b * sAb;
    const __half* Bb = Bg + (long long)b * sBb;

    const int warp = tid >> 5, lane = tid & 31;
    const int gr = lane >> 2, t = lane & 3;
    const int mW = (warp >> 2) * 64, nW = (warp & 3) * 64;

    float acc[4][8][4];
    #pragma unroll
    for (int mi = 0; mi < 4; mi++)
        #pragma unroll
        for (int ni = 0; ni < 8; ni++)
            #pragma unroll
            for (int e = 0; e < 4; e++) acc[mi][ni][e] = 0.f;

    auto load_tile = [&](int st, int kt) {
        uint32_t sa = sbase + st * WSTAGE;
        #pragma unroll
        for (int i = 0; i < 4; i++) {                       // A: 1024 chunks
            int cq = tid + i * 256;
            int r = cq >> 3, c = cq & 7;
            const __half* g = Ab + (m0 + r) * lda + kt + c * 8;
            cp_async16(sa + r * 128 + ((c ^ (r & 7)) << 4), g);
        }
        uint32_t sb = sa + 16384;
        #pragma unroll
        for (int i = 0; i < 8; i++) {                       // B: 2048 chunks
            int cq = tid + i * 256;
            int r = cq >> 3, c = cq & 7;
            const __half* g = Bb + (long long)(n0 + r) * ldb + kt + c * 8;
            cp_async16(sb + r * 128 + ((c ^ (r & 7)) << 4), g);
        }
    };

    const int nK = K / 64;                                  // 64 for agg
    load_tile(0, 0); cp_commit();
    load_tile(1, 64); cp_commit();
    load_tile(2, 128); cp_commit();

    for (int tt = 0; tt < nK; tt++) {
        int rem = nK - 1 - tt;
        if (rem >= 2) cp_wait<2>(); else if (rem == 1) cp_wait<1>(); else cp_wait<0>();
        __syncthreads();
        if (tt + 3 < nK) { load_tile((tt + 3) & 3, (tt + 3) * 64); cp_commit(); }

        uint32_t sa = sbase + (tt & 3) * WSTAGE;
        uint32_t sb = sa + 16384;

        #pragma unroll
        for (int G = 0; G < 4; G++) {
            const int chunk = (G << 1) | (t >> 1);
            const uint32_t swo = ((chunk ^ gr) << 4) + ((t & 1) << 3);
            uint32_t a[4][4];
            #pragma unroll
            for (int mi = 0; mi < 4; mi++) {
                uint32_t ra = sa + (mW + mi * 16 + gr) * 128 + swo;
                lds64(a[mi][0], a[mi][2], ra);
                lds64(a[mi][1], a[mi][3], ra + 1024);
            }
            #pragma unroll
            for (int ni = 0; ni < 8; ni++) {
                uint32_t bf[2];
                lds64(bf[0], bf[1], sb + (nW + ni * 8 + gr) * 128 + swo);
                #pragma unroll
                for (int mi = 0; mi < 4; mi++)
                    mma_f16(acc[mi][ni], a[mi], bf);
            }
        }
    }
    __syncthreads();

    // ---------------- epilogue ----------------
    const __half* selfb = selfg + (long long)b * sSelfb;
    #pragma unroll
    for (int mi = 0; mi < 4; mi++) {
        #pragma unroll
        for (int rr = 0; rr < 2; rr++) {
            int m_loc = mW + mi * 16 + gr + rr * 8;
            long long m = m0 + m_loc;
            float d = ds[(long long)b * NNODE + m];
            #pragma unroll
            for (int ni = 0; ni < 8; ni++) {
                int col = n0 + nW + ni * 8 + 2 * t;
                float v0 = acc[mi][ni][rr * 2 + 0];
                float v1 = acc[mi][ni][rr * 2 + 1];
                float2 sv = __half22float2(*(const __half2*)(selfb + m * ldself + col));
                if (EPI == 0) {
                    v0 = d * (v0 + sv.x);
                    v1 = d * (v1 + sv.y);
                    int g16 = col >> 4, lp = (col >> 1) & 7;
                    __half* Ch = (__half*)Cg + (long long)b * sCb;
                    *(__half2*)(Ch + m * ldc + (g16 << 4) + (pos8(lp) << 1)) =
                        __floats2half2_rn(v0, v1);
                } else {  // EPI == 3
                    v0 = fmaf(d, v0 + sv.x, bias[col]);
                    v1 = fmaf(d, v1 + sv.y, bias[col + 1]);
                    float* Cf = (float*)Cg + (long long)b * sCb;
                    *(float2*)(Cf + m * ldc + col) = make_float2(v0, v1);
                }
            }
        }
    }
}

// ===========================================================================
// NARROW feature GEMM (unchanged from R5): CTA 128x128, 4 warps, 2-stage,
// occ 3.  EPI 1: H = relu(acc+bias) -> half interleaved.
//         EPI 2: P2t[n][m] = ds[m]*acc (T+interleave) ; P2[m][n] plain.
// ===========================================================================
static constexpr int STAGE_BYTES = 32768;
static constexpr int SMEM_BYTES = 2 * STAGE_BYTES;     // 64 KB

template <int EPI>
__global__ void __launch_bounds__(128, 3) gemm_f16(
    const __half* __restrict__ Ag, const __half* __restrict__ Bg, void* __restrict__ Cg,
    const float* __restrict__ ds, const float* __restrict__ bias,
    __half* __restrict__ C2g,
    int K, long long lda, long long ldb, long long ldc) {

    extern __shared__ char smem[];
    const uint32_t sbase = smem_u32(smem);

    const int tid = threadIdx.x;
    const long long m0 = (long long)blockIdx.y * 128;
    const int n0 = blockIdx.x * 128;

    const __half* Ab = Ag;
    const __half* Bb = Bg;

    const int warp = tid >> 5, lane = tid & 31;
    const int gr = lane >> 2, t = lane & 3;
    const int mW = (warp >> 1) * 64, nW = (warp & 1) * 64;

    float acc[4][8][4];
    #pragma unroll
    for (int mi = 0; mi < 4; mi++)
        #pragma unroll
        for (int ni = 0; ni < 8; ni++)
            #pragma unroll
            for (int e = 0; e < 4; e++) acc[mi][ni][e] = 0.f;

    auto load_tile = [&](int st, int kt) {
        uint32_t sa = sbase + st * STAGE_BYTES;
        #pragma unroll
        for (int i = 0; i < 8; i++) {
            int cq = tid + i * 128;
            int r = cq >> 3, c = cq & 7;
            const __half* g = Ab + (m0 + r) * lda + kt + c * 8;
            cp_async16(sa + r * 128 + ((c ^ (r & 7)) << 4), g);
        }
        uint32_t sb = sa + 16384;
        #pragma unroll
        for (int i = 0; i < 8; i++) {
            int cq = tid + i * 128;
            int r = cq >> 3, c = cq & 7;
            const __half* g = Bb + (long long)(n0 + r) * ldb + kt + c * 8;
            cp_async16(sb + r * 128 + ((c ^ (r & 7)) << 4), g);
        }
    };

    const int nK = K / 64;
    load_tile(0, 0); cp_commit();

    for (int tt = 0; tt < nK; tt++) {
        if (tt + 1 < nK) { load_tile((tt + 1) & 1, (tt + 1) * 64); cp_commit(); cp_wait<1>(); }
        else cp_wait<0>();
        __syncthreads();

        uint32_t sa = sbase + (tt & 1) * STAGE_BYTES;
        uint32_t sb = sa + 16384;

        #pragma unroll
        for (int G = 0; G < 4; G++) {
            const int chunk = (G << 1) | (t >> 1);
            const uint32_t swo = ((chunk ^ gr) << 4) + ((t & 1) << 3);
            uint32_t a[4][4];
            #pragma unroll
            for (int mi = 0; mi < 4; mi++) {
                uint32_t ra = sa + (mW + mi * 16 + gr) * 128 + swo;
                lds64(a[mi][0], a[mi][2], ra);
                lds64(a[mi][1], a[mi][3], ra + 1024);
            }
            #pragma unroll
            for (int ni = 0; ni < 8; ni++) {
                uint32_t bf[2];
                lds64(bf[0], bf[1], sb + (nW + ni * 8 + gr) * 128 + swo);
                #pragma unroll
                for (int mi = 0; mi < 4; mi++)
                    mma_f16(acc[mi][ni], a[mi], bf);
            }
        }
        __syncthreads();
    }

    if (EPI == 2) {
        __half* sT = (__half*)smem;
        const long long gmb = (long long)blockIdx.y * 128;
        #pragma unroll
        for (int mi = 0; mi < 4; mi++) {
            #pragma unroll
            for (int rr = 0; rr < 2; rr++) {
                int m_loc = mW + mi * 16 + gr + rr * 8;
                long long gm = gmb + m_loc;
                float d = ds[gm];
                #pragma unroll
                for (int ni = 0; ni < 8; ni++) {
                    int n_loc = nW + ni * 8 + 2 * t;
                    float v0 = d * acc[mi][ni][rr * 2 + 0];
                    float v1 = d * acc[mi][ni][rr * 2 + 1];
                    __half2 hv = __floats2half2_rn(v0, v1);
                    *(__half2*)(sT + m_loc * 136 + n_loc) = hv;
                    *(__half2*)(C2g + gm * ldc + n0 + n_loc) = hv;   // P2 plain
                }
            }
        }
        __syncthreads();
        int bo = (int)(gmb >> 12);
        long long m0loc = gmb & 4095;
        __half* Ct = (__half*)Cg + (long long)bo * OUTC * NNODE
                   + (long long)(n0 + tid) * NNODE + m0loc;
        #pragma unroll
        for (int mg = 0; mg < 8; mg++) {
            __half2 ph[8];
            #pragma unroll
            for (int pp = 0; pp < 8; pp++) {
                int mA = mg * 16 + 2 * pp;
                ph[pos8(pp)] = __halves2half2(sT[mA * 136 + tid], sT[(mA + 1) * 136 + tid]);
            }
            uint4* dst = (uint4*)(Ct + mg * 16);
            dst[0] = *(uint4*)&ph[0];
            dst[1] = *(uint4*)&ph[4];
        }
        return;
    }

    // EPI == 1
    #pragma unroll
    for (int mi = 0; mi < 4; mi++) {
        #pragma unroll
        for (int rr = 0; rr < 2; rr++) {
            int m_loc = mW + mi * 16 + gr + rr * 8;
            long long m = m0 + m_loc;
            #pragma unroll
            for (int ni = 0; ni < 8; ni++) {
                int col = n0 + nW + ni * 8 + 2 * t;
                float v0 = fmaxf(acc[mi][ni][rr * 2 + 0] + bias[col], 0.f);
                float v1 = fmaxf(acc[mi][ni][rr * 2 + 1] + bias[col + 1], 0.f);
                int g16 = col >> 4, lp = (col >> 1) & 7;
                __half* Ch = (__half*)Cg;
                *(__half2*)(Ch + m * ldc + (g16 << 4) + (pos8(lp) << 1)) =
                    __floats2half2_rn(v0, v1);
            }
        }
    }
}

// ---------------------------------------------------------------------------
// launch
// ---------------------------------------------------------------------------
extern "C" void kernel_launch(void* const* d_in, const int* in_sizes, int n_in,
                              void* d_out, int out_size) {
    const float* x  = (const float*)d_in[0];
    const float* A  = (const float*)d_in[1];
    const float* W1 = (const float*)d_in[2];
    const float* b1 = (const float*)d_in[3];
    const float* W2 = (const float*)d_in[4];
    const float* b2 = (const float*)d_in[5];
    float* out = (float*)d_out;

    float* ds;
    __half *Ar, *xs, *xst, *Z1, *H, *P2t, *P2, *W1t, *W2t;
    cudaGetSymbolAddress((void**)&ds,  g_ds);
    cudaGetSymbolAddress((void**)&Ar,  g_Ar);
    cudaGetSymbolAddress((void**)&xs,  g_xs);
    cudaGetSymbolAddress((void**)&xst, g_xst);
    cudaGetSymbolAddress((void**)&Z1,  g_Z1);
    cudaGetSymbolAddress((void**)&H,   g_H);
    cudaGetSymbolAddress((void**)&P2t, g_P2t);
    cudaGetSymbolAddress((void**)&P2,  g_P2);
    cudaGetSymbolAddress((void**)&W1t, g_W1t);
    cudaGetSymbolAddress((void**)&W2t, g_W2t);

    cudaFuncSetAttribute(gemm_f16_wide<0>, cudaFuncAttributeMaxDynamicSharedMemorySize, WSMEM);
    cudaFuncSetAttribute(gemm_f16_wide<3>, cudaFuncAttributeMaxDynamicSharedMemorySize, WSMEM);
    cudaFuncSetAttribute(gemm_f16<1>, cudaFuncAttributeMaxDynamicSharedMemorySize, SMEM_BYTES);
    cudaFuncSetAttribute(gemm_f16<2>, cudaFuncAttributeMaxDynamicSharedMemorySize, SMEM_BYTES);

    // prep
    prep_A_kernel<<<BATCH * NNODE, 256>>>(A, Ar, ds);
    prep_x_kernel<<<dim3(NNODE / 32, INC / 32, BATCH), 256>>>(x, ds, xs, xst);
    prep_W_kernel<<<(HIDC * (INC / 2) + 255) / 256, 256>>>(W1, W1t, INC, HIDC);
    prep_W_kernel<<<(OUTC * (HIDC / 2) + 255) / 256, 256>>>(W2, W2t, HIDC, OUTC);

    // G1: Z1 = ds∘(A@xs + xs)   (wide agg, per-batch, N=256, single A pass)
    gemm_f16_wide<0><<<dim3(INC / 256, NNODE / 128, BATCH), 256, WSMEM>>>(
        Ar, xst, Z1, xs, ds, nullptr,
        NNODE, NNODE, NNODE, INC, INC,
        (long long)NNODE * NNODE, (long long)INC * NNODE,
        (long long)NNODE * INC, (long long)NNODE * INC);

    // G2: H = relu(Z1@W1 + b1)
    gemm_f16<1><<<dim3(HIDC / 128, MT / 128, 1), 128, SMEM_BYTES>>>(
        Z1, W1t, H, ds, b1, nullptr, INC, INC, INC, HIDC);

    // G3: P2t = (ds∘(H@W2))^T + P2 plain copy
    gemm_f16<2><<<dim3(OUTC / 128, MT / 128, 1), 128, SMEM_BYTES>>>(
        H, W2t, P2t, ds, nullptr, P2, HIDC, HIDC, HIDC, OUTC);

    // G4: out = ds∘(A@P2 + P2) + b2   (wide agg)
    gemm_f16_wide<3><<<dim3(OUTC / 256, NNODE / 128, BATCH), 256, WSMEM>>>(
        Ar, P2t, out, P2, ds, b2,
        NNODE, NNODE, NNODE, OUTC, OUTC,
        (long long)NNODE * NNODE, (long long)OUTC * NNODE,
        (long long)NNODE * OUTC, (long long)NNODE * OUTC);
}